// round 11
// baseline (speedup 1.0000x reference)
#include <cuda_runtime.h>
#include <math.h>

#define DD 512
#define MM 2048
#define BB 4
#define KK 8
#define NN 8192
#define MB_ (MM*BB)               // 8192 floats per h_all row
#define RPB 8                     // rows per block (4 pairs, pipelined)
#define NPAIRS (RPB/2)
#define EPSV 1e-8f

// Scratch (device globals: allocation-free rule)
__device__ float g_Vt[(size_t)MM*BB*DD];   // 16 MB: Vt[(m*B+b)*D + d]
__device__ float g_esum[MM];
__device__ float g_counts[MM];
__device__ float g_acc[3];                 // cap, rec, unc (sums over rows)
__device__ unsigned g_done;

// packed f32x2 helpers
#define PACKF2(out, lo, hi)  asm("mov.b64 %0, {%1, %2};" : "=l"(out) : "f"(lo), "f"(hi))
#define UNPACKF2(lo, hi, in) asm("mov.b64 {%0, %1}, %2;" : "=f"(lo), "=f"(hi) : "l"(in))
#define FMAF2(d, a, b, c)    asm("fma.rn.f32x2 %0, %1, %2, %3;" : "=l"(d) : "l"(a), "l"(b), "l"(c))

// Tiled transpose V (D, M*B) -> Vt (M*B, D); block (0,0) also zeroes accumulators.
__global__ void transpose_kernel(const float* __restrict__ V) {
    __shared__ float tile[32][33];
    if (blockIdx.x == 0 && blockIdx.y == 0) {
        int t = threadIdx.y * 32 + threadIdx.x;
        #pragma unroll
        for (int j = 0; j < 8; j++) { g_esum[t + 256*j] = 0.0f; g_counts[t + 256*j] = 0.0f; }
        if (t < 3) g_acc[t] = 0.0f;
        if (t == 0) g_done = 0u;
    }
    int mb0 = blockIdx.x * 32;
    int d0  = blockIdx.y * 32;
    int tx = threadIdx.x, ty = threadIdx.y;   // 32 x 8
    #pragma unroll
    for (int i = 0; i < 32; i += 8)
        tile[ty + i][tx] = V[(size_t)(d0 + ty + i) * MB_ + mb0 + tx];
    __syncthreads();
    #pragma unroll
    for (int i = 0; i < 32; i += 8)
        g_Vt[(size_t)(mb0 + ty + i) * DD + d0 + tx] = tile[tx][ty + i];
}

// warp argmax over (value-bits desc, index asc): REDUX pair.
__device__ __forceinline__ void warp_argmax(unsigned vbits, int m,
                                            unsigned &win_v, int &win_m) {
    unsigned mx = __reduce_max_sync(0xffffffffu, vbits);
    unsigned cand = (vbits == mx) ? (unsigned)m : 0xffffffffu;
    win_m = (int)__reduce_min_sync(0xffffffffu, cand);
    win_v = mx;
}

// One B1 round: extract current max of both rows' register sets, publish candidates.
__device__ __forceinline__ void b1_round(unsigned ebA[8], unsigned ebB[8],
    int mbase, int lane, int warp, int kk,
    unsigned* cvAb, int* cmAb, unsigned* cvBb, int* cmBb)
{
    unsigned bvA = ebA[0]; int bjA = 0;
    #pragma unroll
    for (int j = 1; j < 8; j++) if (ebA[j] > bvA) { bvA = ebA[j]; bjA = j; }
    int bmA = mbase + 32 * bjA;
    unsigned bvB = ebB[0]; int bjB = 0;
    #pragma unroll
    for (int j = 1; j < 8; j++) if (ebB[j] > bvB) { bvB = ebB[j]; bjB = j; }
    int bmB = mbase + 32 * bjB;

    unsigned wvA; int wmA; warp_argmax(bvA, bmA, wvA, wmA);
    unsigned wvB; int wmB; warp_argmax(bvB, bmB, wvB, wmB);

    #pragma unroll
    for (int j = 0; j < 8; j++) {
        if (wmA == mbase + 32 * j) ebA[j] = 0u;
        if (wmB == mbase + 32 * j) ebB[j] = 0u;
    }
    if (lane == 0) {
        cvAb[warp * 8 + kk] = wvA; cmAb[warp * 8 + kk] = wmA;
        cvBb[warp * 8 + kk] = wvB; cmBb[warp * 8 + kk] = wmB;
    }
}

// One B2 merge round over the 64-candidate lists.
__device__ __forceinline__ void b2_round(unsigned &c0, unsigned &c1, int &m0, int &m1,
                                         int &selk, float &capadd)
{
    bool p0 = (c0 > c1) || (c0 == c1 && m0 < m1);
    unsigned bv = p0 ? c0 : c1;
    int      bm = p0 ? m0 : m1;
    unsigned wv; int wm; warp_argmax(bv, bm, wv, wm);
    selk = wm;
    capadd = __uint_as_float(wv);
    if (m0 == wm) c0 = 0u;
    if (m1 == wm) c1 = 0u;
}

// One Phase-D step for expert m: 4 d's per thread, f32 dictionary, packed FFMA2.
__device__ __forceinline__ void d_kk(const float4* __restrict__ hrow, int m, int d0,
                                     unsigned long long &acc01, unsigned long long &acc23)
{
    float4 h = hrow[m];                        // uniform address, cache hit
    const float* vb = g_Vt + (size_t)m * (BB * DD) + d0;
    float4 v0 = *(const float4*)(vb);
    float4 v1 = *(const float4*)(vb + DD);
    float4 v2 = *(const float4*)(vb + 2 * DD);
    float4 v3 = *(const float4*)(vb + 3 * DD);
    unsigned long long hb, vv;
    PACKF2(hb, h.x, h.x);
    PACKF2(vv, v0.x, v0.y); FMAF2(acc01, hb, vv, acc01);
    PACKF2(vv, v0.z, v0.w); FMAF2(acc23, hb, vv, acc23);
    PACKF2(hb, h.y, h.y);
    PACKF2(vv, v1.x, v1.y); FMAF2(acc01, hb, vv, acc01);
    PACKF2(vv, v1.z, v1.w); FMAF2(acc23, hb, vv, acc23);
    PACKF2(hb, h.z, h.z);
    PACKF2(vv, v2.x, v2.y); FMAF2(acc01, hb, vv, acc01);
    PACKF2(vv, v2.z, v2.w); FMAF2(acc23, hb, vv, acc23);
    PACKF2(hb, h.w, h.w);
    PACKF2(vv, v3.x, v3.y); FMAF2(acc01, hb, vv, acc01);
    PACKF2(vv, v3.z, v3.w); FMAF2(acc23, hb, vv, acc23);
}

// Phase A for one pair: stream both rows, energies to regs + exclusive smem slots.
__device__ __forceinline__ void phase_a(const float* __restrict__ h_all, int nA,
                                        int mbase, unsigned ebA[8], unsigned ebB[8],
                                        float* s_esum)
{
    const float4* hA = (const float4*)(h_all + (size_t)nA * MB_);
    const float4* hB = (const float4*)(h_all + (size_t)(nA + 1) * MB_);
    #pragma unroll
    for (int j = 0; j < 8; j++) {
        float4 a = __ldcs(&hA[mbase + 32 * j]);
        float4 b = __ldcs(&hB[mbase + 32 * j]);
        float ea = fmaf(a.x, a.x, fmaf(a.y, a.y, fmaf(a.z, a.z, a.w * a.w)));
        float ec = fmaf(b.x, b.x, fmaf(b.y, b.y, fmaf(b.z, b.z, b.w * b.w)));
        s_esum[mbase + 32 * j] += ea + ec;     // exclusive slot, no atomics
        ebA[j] = __float_as_uint(ea);
        ebB[j] = __float_as_uint(ec);
    }
}

__global__ __launch_bounds__(256, 4)
void main_kernel(const float* __restrict__ x_flat,
                 const float* __restrict__ h_all,
                 float* __restrict__ out) {
    __shared__ unsigned cvA[2][64], cvB[2][64];
    __shared__ int      cmA[2][64], cmB[2][64];
    __shared__ int      sel_sh[2][2][KK];      // [buf][half][k]
    __shared__ float    s_esum[MM];            // exclusive per-thread slots
    __shared__ float    red_a[8], red_b[8];
    __shared__ unsigned s_last;

    const int t = threadIdx.x;
    const int warp = t >> 5, lane = t & 31;
    const int mbase = warp * 256 + lane;
    const int half = warp >> 2;                // 0: row A duty, 1: row B duty
    const int t2 = t & 127;
    const int d0 = 4 * t2;
    const int nbase = blockIdx.x * RPB;
    const bool merger = (warp & 3) == 0;       // warps 0 and 4 do B2

    #pragma unroll
    for (int j = 0; j < 8; j++) s_esum[mbase + 32 * j] = 0.0f;

    float unc_acc = 0.0f, rec_acc = 0.0f, cap_acc = 0.0f;

    float* out_hs  = out;                          // (N, K, B)
    float* out_idx = out + (size_t)NN * KK * BB;   // (N, K) as float

    unsigned ebA[8], ebB[8];

    // ---- prologue: A(0), B1(0), bar, B2(0) by mergers, bar ----
    phase_a(h_all, nbase, mbase, ebA, ebB, s_esum);
    #pragma unroll
    for (int kk = 0; kk < KK; kk++)
        b1_round(ebA, ebB, mbase, lane, warp, kk, cvA[0], cmA[0], cvB[0], cmB[0]);
    __syncthreads();
    if (merger) {
        const unsigned* cv = half ? cvB[0] : cvA[0];
        const int*      cm = half ? cmB[0] : cmA[0];
        unsigned c0 = cv[lane], c1 = cv[lane + 32];
        int      m0 = cm[lane], m1 = cm[lane + 32];
        #pragma unroll
        for (int kk = 0; kk < KK; kk++) {
            int wm; float capadd;
            b2_round(c0, c1, m0, m1, wm, capadd);
            if (lane == 0) { sel_sh[0][half][kk] = wm; cap_acc += capadd; }
        }
    }
    __syncthreads();

    // ---- pipelined main loop ----
    #pragma unroll 1
    for (int i = 0; i < NPAIRS - 1; i++) {
        const int buf = i & 1, bufn = (i + 1) & 1;
        const int ncur = nbase + 2 * i + half;
        const float4* hcur = (const float4*)(h_all + (size_t)ncur * MB_);

        // S1: A(i+1); B1(i+1) interleaved with D(i) kk0..3; C(i)
        phase_a(h_all, nbase + 2 * (i + 1), mbase, ebA, ebB, s_esum);
        unsigned long long acc01, acc23;
        PACKF2(acc01, 0.0f, 0.0f);
        PACKF2(acc23, 0.0f, 0.0f);
        #pragma unroll
        for (int kk = 0; kk < KK; kk++) {
            b1_round(ebA, ebB, mbase, lane, warp, kk,
                     cvA[bufn], cmA[bufn], cvB[bufn], cmB[bufn]);
            if (kk < 4) d_kk(hcur, sel_sh[buf][half][kk], d0, acc01, acc23);
        }
        if (merger && lane < KK) {
            int mym = sel_sh[buf][half][lane];
            out_idx[(size_t)ncur * KK + lane] = (float)mym;
            float4 h = hcur[mym];
            ((float4*)(out_hs + (size_t)ncur * KK * BB))[lane] = h;
            atomicAdd(&g_counts[mym], 1.0f);
        }
        __syncthreads();

        // S2: mergers run B2(i+1) (interleaved with D(i) kk4..7); others D(i) kk4..7
        if (merger) {
            const unsigned* cv = half ? cvB[bufn] : cvA[bufn];
            const int*      cm = half ? cmB[bufn] : cmA[bufn];
            unsigned c0 = cv[lane], c1 = cv[lane + 32];
            int      m0 = cm[lane], m1 = cm[lane + 32];
            #pragma unroll
            for (int kk = 0; kk < KK; kk++) {
                int wm; float capadd;
                b2_round(c0, c1, m0, m1, wm, capadd);
                if (lane == 0) { sel_sh[bufn][half][kk] = wm; cap_acc += capadd; }
                if (kk < 4) d_kk(hcur, sel_sh[buf][half][kk + 4], d0, acc01, acc23);
            }
        } else {
            #pragma unroll
            for (int kk = 4; kk < KK; kk++)
                d_kk(hcur, sel_sh[buf][half][kk], d0, acc01, acc23);
        }
        // residual(i)
        {
            float ax, ay, az, aw;
            UNPACKF2(ax, ay, acc01);
            UNPACKF2(az, aw, acc23);
            float4 xv = __ldcs((const float4*)(x_flat + (size_t)ncur * DD + d0));
            float rx = xv.x - ax, ry = xv.y - ay, rz = xv.z - az, rw = xv.w - aw;
            unc_acc += rx * rx + ry * ry + rz * rz + rw * rw;
            rec_acc += ax * ax + ay * ay + az * az + aw * aw;
        }
        __syncthreads();   // publishes sel_sh[bufn] for next S1
    }

    // ---- epilogue: pair NPAIRS-1 ----
    {
        const int bufL = (NPAIRS - 1) & 1;
        const int ncur = nbase + 2 * (NPAIRS - 1) + half;
        const float4* hcur = (const float4*)(h_all + (size_t)ncur * MB_);
        unsigned long long acc01, acc23;
        PACKF2(acc01, 0.0f, 0.0f);
        PACKF2(acc23, 0.0f, 0.0f);
        #pragma unroll
        for (int kk = 0; kk < KK; kk++)
            d_kk(hcur, sel_sh[bufL][half][kk], d0, acc01, acc23);
        if (merger && lane < KK) {
            int mym = sel_sh[bufL][half][lane];
            out_idx[(size_t)ncur * KK + lane] = (float)mym;
            float4 h = hcur[mym];
            ((float4*)(out_hs + (size_t)ncur * KK * BB))[lane] = h;
            atomicAdd(&g_counts[mym], 1.0f);
        }
        float ax, ay, az, aw;
        UNPACKF2(ax, ay, acc01);
        UNPACKF2(az, aw, acc23);
        float4 xv = __ldcs((const float4*)(x_flat + (size_t)ncur * DD + d0));
        float rx = xv.x - ax, ry = xv.y - ay, rz = xv.z - az, rw = xv.w - aw;
        unc_acc += rx * rx + ry * ry + rz * rz + rw * rw;
        rec_acc += ax * ax + ay * ay + az * az + aw * aw;
    }

    // ---- flush block accumulators (once per kernel) ----
    #pragma unroll
    for (int j = 0; j < 8; j++)
        atomicAdd(&g_esum[mbase + 32 * j], s_esum[mbase + 32 * j]);
    #pragma unroll
    for (int off = 16; off; off >>= 1) {
        unc_acc += __shfl_down_sync(0xffffffffu, unc_acc, off);
        rec_acc += __shfl_down_sync(0xffffffffu, rec_acc, off);
    }
    if (lane == 0) {
        atomicAdd(&g_acc[2], unc_acc);
        atomicAdd(&g_acc[1], rec_acc);
        if (merger) atomicAdd(&g_acc[0], cap_acc);
    }
    __threadfence();
    __syncthreads();
    if (t == 0) s_last = (atomicAdd(&g_done, 1u) == gridDim.x - 1) ? 1u : 0u;
    __syncthreads();
    if (!s_last) return;

    // ---- last-block finalize ----
    {
        float s = 0.0f;
        #pragma unroll
        for (int j = 0; j < 8; j++) s += __ldcg(&g_esum[t + 256 * j]);
        #pragma unroll
        for (int off = 16; off; off >>= 1) s += __shfl_down_sync(0xffffffffu, s, off);
        if (lane == 0) red_a[warp] = s;
        __syncthreads();
        __shared__ float s_denom;
        if (t == 0) {
            float tot = 0.0f;
            #pragma unroll
            for (int w = 0; w < 8; w++) tot += red_a[w];
            s_denom = fmaxf(tot / (float)NN, EPSV);
        }
        __syncthreads();
        const float denom = s_denom;

        float ent = 0.0f, low = 0.0f, dead = 0.0f;
        const float expected = (float)KK / (float)MM * (float)NN;  // 32
        #pragma unroll
        for (int j = 0; j < 8; j++) {
            int m = t + 256 * j;
            float avg = __ldcg(&g_esum[m]) / (float)NN;
            float p = fmaxf(avg / denom, EPSV);
            ent += -p * logf(p);
            float c = __ldcg(&g_counts[m]);
            if (c <= 0.1f * expected)  low  += 1.0f;
            if (c <= 0.01f * expected) dead += 1.0f;
        }
        #pragma unroll
        for (int off = 16; off; off >>= 1) {
            ent  += __shfl_down_sync(0xffffffffu, ent,  off);
            low  += __shfl_down_sync(0xffffffffu, low,  off);
            dead += __shfl_down_sync(0xffffffffu, dead, off);
        }
        if (lane == 0) { red_a[warp] = ent; red_b[warp] = low; cvA[0][warp] = __float_as_uint(dead); }
        __syncthreads();
        if (t == 0) {
            float E = 0.0f, L = 0.0f, Dd = 0.0f;
            #pragma unroll
            for (int w = 0; w < 8; w++) {
                E += red_a[w]; L += red_b[w]; Dd += __uint_as_float(cvA[0][w]);
            }
            float entropy = E / logf((float)MM);
            float cap = __ldcg(&g_acc[0]) / (float)NN;
            float rec = __ldcg(&g_acc[1]) / (float)NN;
            float unc = __ldcg(&g_acc[2]) / (float)NN;
            size_t OFF = (size_t)NN * KK * BB + (size_t)NN * KK;  // 327680
            out[OFF + 0] = cap;
            out[OFF + 1] = rec;
            out[OFF + 2] = unc;
            out[OFF + 3] = entropy;
            out[OFF + 4] = unc + 0.01f * (1.0f - entropy);
            out[OFF + 5] = L;
            out[OFF + 6] = Dd;
        }
    }
}

extern "C" void kernel_launch(void* const* d_in, const int* in_sizes, int n_in,
                              void* d_out, int out_size) {
    const float* x_flat = (const float*)d_in[0];   // (N, D)
    const float* h_all  = (const float*)d_in[1];   // (N, M, B)
    const float* V      = (const float*)d_in[2];   // (D, M, B)
    float* out = (float*)d_out;

    dim3 tb(32, 8);
    dim3 tg(MB_ / 32, DD / 32);    // (256, 16)
    transpose_kernel<<<tg, tb>>>(V);

    main_kernel<<<NN / RPB, 256>>>(x_flat, h_all, out);
}